// round 1
// baseline (speedup 1.0000x reference)
#include <cuda_runtime.h>

// Geometric product in Cl(3,0,1): out[n,k] = sum_{i,j} a[n,i] b[n,j] C[i,j,k]
// Structure constants baked in at compile time (metric = 1,1,1,0).
// Memory-bound: 384 MB of pure streaming traffic; 192 FMAs per row.

static __host__ __device__ constexpr int cayley_sign(int A, int B) {
    // Degenerate generator e3 (metric 0): any shared bit-3 kills the term.
    if (A & B & 8) return 0;
    // Reordering sign: count transpositions.
    int s = 0;
    int sa = A >> 1;
    while (sa) {
        int x = sa & B;
        while (x) { s += 1; x &= (x - 1); }
        sa >>= 1;
    }
    // metric[0..2] = +1 contribute nothing further.
    return (s & 1) ? -1 : 1;
}

__global__ void __launch_bounds__(256, 8)
gp_kernel(const float4* __restrict__ a4,
          const float4* __restrict__ b4,
          float4* __restrict__ o4,
          int n_rows) {
    const int row = blockIdx.x * blockDim.x + threadIdx.x;
    if (row >= n_rows) return;

    // Load 16 floats of a and b (4x float4 each). Within a warp the 4
    // consecutive vector loads fully cover every 128B line touched, so
    // DRAM sectors are 100% utilized.
    float a[16], b[16], c[16];

    {
        const float4 v0 = a4[row * 4 + 0];
        const float4 v1 = a4[row * 4 + 1];
        const float4 v2 = a4[row * 4 + 2];
        const float4 v3 = a4[row * 4 + 3];
        a[0]=v0.x; a[1]=v0.y; a[2]=v0.z; a[3]=v0.w;
        a[4]=v1.x; a[5]=v1.y; a[6]=v1.z; a[7]=v1.w;
        a[8]=v2.x; a[9]=v2.y; a[10]=v2.z; a[11]=v2.w;
        a[12]=v3.x; a[13]=v3.y; a[14]=v3.z; a[15]=v3.w;
    }
    {
        const float4 v0 = b4[row * 4 + 0];
        const float4 v1 = b4[row * 4 + 1];
        const float4 v2 = b4[row * 4 + 2];
        const float4 v3 = b4[row * 4 + 3];
        b[0]=v0.x; b[1]=v0.y; b[2]=v0.z; b[3]=v0.w;
        b[4]=v1.x; b[5]=v1.y; b[6]=v1.z; b[7]=v1.w;
        b[8]=v2.x; b[9]=v2.y; b[10]=v2.z; b[11]=v2.w;
        b[12]=v3.x; b[13]=v3.y; b[14]=v3.z; b[15]=v3.w;
    }

    #pragma unroll
    for (int k = 0; k < 16; ++k) c[k] = 0.0f;

    // Fully unrolled: after unrolling, cayley_sign(A,B) is a compile-time
    // constant; zero terms vanish, leaving 192 FFMAs in a straight line.
    #pragma unroll
    for (int A = 0; A < 16; ++A) {
        #pragma unroll
        for (int B = 0; B < 16; ++B) {
            const int s = cayley_sign(A, B);
            if (s == 1) {
                c[A ^ B] = fmaf(a[A], b[B], c[A ^ B]);
            } else if (s == -1) {
                c[A ^ B] = fmaf(-a[A], b[B], c[A ^ B]);
            }
        }
    }

    o4[row * 4 + 0] = make_float4(c[0],  c[1],  c[2],  c[3]);
    o4[row * 4 + 1] = make_float4(c[4],  c[5],  c[6],  c[7]);
    o4[row * 4 + 2] = make_float4(c[8],  c[9],  c[10], c[11]);
    o4[row * 4 + 3] = make_float4(c[12], c[13], c[14], c[15]);
}

extern "C" void kernel_launch(void* const* d_in, const int* in_sizes, int n_in,
                              void* d_out, int out_size) {
    const float4* a4 = (const float4*)d_in[0];
    const float4* b4 = (const float4*)d_in[1];
    // d_in[2] is the Cayley tensor; its values are baked in at compile time.
    float4* o4 = (float4*)d_out;

    const int n_rows = in_sizes[0] / 16;
    const int threads = 256;
    const int blocks = (n_rows + threads - 1) / threads;
    gp_kernel<<<blocks, threads>>>(a4, b4, o4, n_rows);
}

// round 2
// speedup vs baseline: 2.5484x; 2.5484x over previous
#include <cuda_runtime.h>

// Geometric product in Cl(3,0,1): out[n,k] = sum_{i,j} a[n,i] b[n,j] C[i,j,k]
// Structure constants baked in at compile time (metric = 1,1,1,0).
//
// R2: smem-staged version. All global LDG/STG are unit-stride per instruction
// (4 L1 wavefronts/instr instead of 16 for the 64B-strided AoS pattern).
// Smem uses an XOR swizzle so every STS/LDS phase is bank-conflict-free.

static __host__ __device__ constexpr int cayley_sign(int A, int B) {
    if (A & B & 8) return 0;            // degenerate generator e3 (metric 0)
    int s = 0;
    int sa = A >> 1;
    while (sa) {
        int x = sa & B;
        while (x) { s += 1; x &= (x - 1); }
        sa >>= 1;
    }
    return (s & 1) ? -1 : 1;
}

// Swizzled position for flat float4 index idx (within a 1024-float4 tile):
//   r = row (idx>>2), c = column-quad (idx&3)
//   pos = 4r | (c ^ ((r>>1)&3))
// Guarantees 8 distinct 16B bank-quads in every 8-lane LDS/STS.128 phase for
// both the unit-stride staging pattern and the per-row read/write pattern.
static __device__ __forceinline__ int swz(int idx) {
    const int r = idx >> 2;
    const int c = idx & 3;
    return (r << 2) | (c ^ ((r >> 1) & 3));
}

__global__ void __launch_bounds__(256)
gp_kernel(const float4* __restrict__ a4,
          const float4* __restrict__ b4,
          float4* __restrict__ o4,
          int n_rows) {
    __shared__ float4 sa[1024];   // 16 KB
    __shared__ float4 sb[1024];   // 16 KB

    const int t     = threadIdx.x;
    const int base4 = blockIdx.x * 1024;          // float4 index of tile start
    const int row0  = blockIdx.x * 256;

    // ---- Stage a and b: unit-stride global loads, swizzled smem writes ----
    if (row0 + 256 <= n_rows) {
        #pragma unroll
        for (int v = 0; v < 4; ++v) {
            const int idx = v * 256 + t;
            const int pos = swz(idx);
            sa[pos] = a4[base4 + idx];
            sb[pos] = b4[base4 + idx];
        }
    } else {
        #pragma unroll
        for (int v = 0; v < 4; ++v) {
            const int idx = v * 256 + t;
            const int pos = swz(idx);
            if ((base4 + idx) < n_rows * 4) {
                sa[pos] = a4[base4 + idx];
                sb[pos] = b4[base4 + idx];
            } else {
                sa[pos] = make_float4(0.f, 0.f, 0.f, 0.f);
                sb[pos] = make_float4(0.f, 0.f, 0.f, 0.f);
            }
        }
    }
    __syncthreads();

    // ---- Each thread reads its own row (conflict-free via swizzle) ----
    float a[16], b[16];
    const int s = (t >> 1) & 3;
    #pragma unroll
    for (int v = 0; v < 4; ++v) {
        const int u = v ^ s;                       // physical quad holding logical quad v
        const float4 va = sa[(t << 2) | u];
        const float4 vb = sb[(t << 2) | u];
        a[v * 4 + 0] = va.x; a[v * 4 + 1] = va.y;
        a[v * 4 + 2] = va.z; a[v * 4 + 3] = va.w;
        b[v * 4 + 0] = vb.x; b[v * 4 + 1] = vb.y;
        b[v * 4 + 2] = vb.z; b[v * 4 + 3] = vb.w;
    }

    // ---- Fully unrolled geometric product: 192 straight-line FFMAs ----
    float c[16];
    #pragma unroll
    for (int k = 0; k < 16; ++k) c[k] = 0.0f;

    #pragma unroll
    for (int A = 0; A < 16; ++A) {
        #pragma unroll
        for (int B = 0; B < 16; ++B) {
            const int sg = cayley_sign(A, B);
            if (sg == 1) {
                c[A ^ B] = fmaf(a[A], b[B], c[A ^ B]);
            } else if (sg == -1) {
                c[A ^ B] = fmaf(-a[A], b[B], c[A ^ B]);
            }
        }
    }

    // ---- Write own output row into sa (own region; no sync needed before) ----
    #pragma unroll
    for (int v = 0; v < 4; ++v) {
        const int u = v ^ s;
        sa[(t << 2) | u] = make_float4(c[v * 4 + 0], c[v * 4 + 1],
                                       c[v * 4 + 2], c[v * 4 + 3]);
    }
    __syncthreads();

    // ---- Gather + unit-stride global stores ----
    if (row0 + 256 <= n_rows) {
        #pragma unroll
        for (int v = 0; v < 4; ++v) {
            const int idx = v * 256 + t;
            o4[base4 + idx] = sa[swz(idx)];
        }
    } else {
        #pragma unroll
        for (int v = 0; v < 4; ++v) {
            const int idx = v * 256 + t;
            if ((base4 + idx) < n_rows * 4)
                o4[base4 + idx] = sa[swz(idx)];
        }
    }
}

extern "C" void kernel_launch(void* const* d_in, const int* in_sizes, int n_in,
                              void* d_out, int out_size) {
    const float4* a4 = (const float4*)d_in[0];
    const float4* b4 = (const float4*)d_in[1];
    // d_in[2] is the Cayley tensor; values are baked in at compile time.
    float4* o4 = (float4*)d_out;

    const int n_rows  = in_sizes[0] / 16;
    const int rows_per_cta = 256;
    const int blocks  = (n_rows + rows_per_cta - 1) / rows_per_cta;
    gp_kernel<<<blocks, 256>>>(a4, b4, o4, n_rows);
}